// round 14
// baseline (speedup 1.0000x reference)
#include <cuda_runtime.h>
#include <cuda_bf16.h>
#include <math.h>
#include <stdint.h>

#define NN   8192
#define FIN  3000
#define FO   64
#define CAP  192
#define KC   94          // ceil(3000/32) K-chunks for feat GEMM
#define KPAD 3008

typedef unsigned long long u64;
typedef unsigned int       u32;

// ---------------- scratch ----------------
__device__ int   g_adj_idx[NN * CAP];
__device__ int   g_adj_cnt[NN];
__device__ float g_dinv[NN];
__device__ int   g_gn_idx[NN * CAP];
__device__ int   g_gn_cnt[NN];
__device__ float g_xw1[NN * FO];
__device__ float g_xaw1[NN * FO];
__device__ float g_pz[NN * FO];
__device__ __nv_bfloat16 g_w1t_hi[FO * KPAD];   // W1^T  [64][3008]
__device__ __nv_bfloat16 g_w1t_lo[FO * KPAD];
__device__ __nv_bfloat16 g_w2t_hi[3072 * FO];   // W2^T  [3072][64]
__device__ __nv_bfloat16 g_w2t_lo[3072 * FO];

// ---------------- mma.sync (sm_80+ PTX; fragment loads are plain LDS) ------
__device__ __forceinline__ void mmabf(float* d, const u32* a, const u32* b) {
    asm volatile("mma.sync.aligned.m16n8k16.row.col.f32.bf16.bf16.f32 "
                 "{%0,%1,%2,%3},{%4,%5,%6,%7},{%8,%9},{%0,%1,%2,%3};"
                 : "+f"(d[0]), "+f"(d[1]), "+f"(d[2]), "+f"(d[3])
                 : "r"(a[0]), "r"(a[1]), "r"(a[2]), "r"(a[3]), "r"(b[0]), "r"(b[1]));
}

// hi/lo bf16 split of 4 floats, packed as 2x(bf16x2)
__device__ __forceinline__ void split4(float4 v, uint2& hi, uint2& lo) {
    __nv_bfloat16 h0 = __float2bfloat16(v.x), h1 = __float2bfloat16(v.y);
    __nv_bfloat16 h2 = __float2bfloat16(v.z), h3 = __float2bfloat16(v.w);
    __nv_bfloat16 l0 = __float2bfloat16(v.x - __bfloat162float(h0));
    __nv_bfloat16 l1 = __float2bfloat16(v.y - __bfloat162float(h1));
    __nv_bfloat16 l2 = __float2bfloat16(v.z - __bfloat162float(h2));
    __nv_bfloat16 l3 = __float2bfloat16(v.w - __bfloat162float(h3));
    hi.x = ((u32)__bfloat16_as_ushort(h1) << 16) | __bfloat16_as_ushort(h0);
    hi.y = ((u32)__bfloat16_as_ushort(h3) << 16) | __bfloat16_as_ushort(h2);
    lo.x = ((u32)__bfloat16_as_ushort(l1) << 16) | __bfloat16_as_ushort(l0);
    lo.y = ((u32)__bfloat16_as_ushort(l3) << 16) | __bfloat16_as_ushort(l2);
}

// ---------------------------------------------------------------------------
// Prep: W1^T and W2^T as bf16 hi/lo, zero-padded.
// ---------------------------------------------------------------------------
__global__ void prep_kernel(const float* __restrict__ W1, const float* __restrict__ W2)
{
    int bx = blockIdx.x, t = threadIdx.x;
    if (bx < 752) {                 // w1t: 64 x 3008
        int idx = bx * 256 + t;
        int n = idx & 63, k = idx >> 6;
        float x = (k < FIN) ? W1[k * 64 + n] : 0.f;
        __nv_bfloat16 h = __float2bfloat16(x);
        __nv_bfloat16 l = __float2bfloat16(x - __bfloat162float(h));
        g_w1t_hi[n * KPAD + k] = h;
        g_w1t_lo[n * KPAD + k] = l;
    } else {                        // w2t: 3072 x 64
        int idx = (bx - 752) * 256 + t;
        int k = idx & 63, n = idx >> 6;
        float x = (n < FIN) ? W2[k * FIN + n] : 0.f;
        __nv_bfloat16 h = __float2bfloat16(x);
        __nv_bfloat16 l = __float2bfloat16(x - __bfloat162float(h));
        g_w2t_hi[n * 64 + k] = h;
        g_w2t_lo[n * 64 + k] = l;
    }
}

// ---------------------------------------------------------------------------
// Fused: blocks [0,256) = feat@W1 / feat_a@W1 via bf16-split mma.sync
//        (64x64 tiles -> 2x parallelism, 40KB smem -> 5 blocks/SM);
//        blocks [256, 256+2*NN) = adjacency / graph_neigh ELL builds.
// A and B tiles double-buffered; one sync per chunk; __ldcs on streams.
// ---------------------------------------------------------------------------
#define DSM_AHI(buf)  (dsm + (buf) * 5120)
#define DSM_ALO(buf)  (dsm + 10240 + (buf) * 5120)
#define DSM_BHI(buf)  (dsm + 20480 + (buf) * 5120)
#define DSM_BLO(buf)  (dsm + 30720 + (buf) * 5120)
#define DSM_BYTES 40960

__global__ void __launch_bounds__(256) fused_build_gemm(
    const float* __restrict__ feat, const float* __restrict__ feat_a,
    const float* __restrict__ adj, const float* __restrict__ gnm)
{
    extern __shared__ __align__(16) unsigned char dsm[];
    __shared__ int wsum[8];

    int t  = threadIdx.x;
    int bx = blockIdx.x;

    if (bx < 256) {
        // ------------------- GEMM role (64x64 tile) -------------------
        int which = bx >> 7;
        int row0  = (bx & 127) * 64;
        const float* A = which ? feat_a : feat;
        float*       C = which ? g_xaw1 : g_xw1;

        int wid = t >> 5, lane = t & 31;
        int wm = wid & 3, wn = wid >> 2;     // 4 warps x 16 rows, 2 warps x 32 cols
        int fr = lane >> 2;                  // groupID
        int fcb = (lane & 3) * 4;            // k-pair byte offset

        float d[4][4];
        #pragma unroll
        for (int ni = 0; ni < 4; ni++)
            #pragma unroll
            for (int j = 0; j < 4; j++) d[ni][j] = 0.f;

        // A-store mapping: 2 float4/thread (64 rows x 8 float4)
        int ar[2], aq[2];
        #pragma unroll
        for (int i = 0; i < 2; i++) { int lin = t + i * 256; ar[i] = lin >> 3; aq[i] = lin & 7; }
        // B: 2 threads/row, each moves 2 uint4 (32 B) -> full 64-B row covered
        int bi = t & 127, bn = bi >> 1, bhalf = bi & 1, bbuf = t >> 7;
        const __nv_bfloat16* bsrc = bbuf ? g_w1t_lo : g_w1t_hi;
        int boff = bn * 80 + bhalf * 32;

        float4 pa[2]; uint4 pb0, pb1;
        // ---- prologue: chunk 0 -> buf0; prefetch chunk 1 into regs ----
        #pragma unroll
        for (int i = 0; i < 2; i++)
            pa[i] = __ldcs((const float4*)(A + (size_t)(row0 + ar[i]) * FIN + aq[i] * 4));
        pb0 = *(const uint4*)(bsrc + (size_t)bn * KPAD + bhalf * 16);
        pb1 = *(const uint4*)(bsrc + (size_t)bn * KPAD + bhalf * 16 + 8);
        #pragma unroll
        for (int i = 0; i < 2; i++) {
            uint2 hi, lo; split4(pa[i], hi, lo);
            *(uint2*)(DSM_AHI(0) + ar[i] * 80 + aq[i] * 8) = hi;
            *(uint2*)(DSM_ALO(0) + ar[i] * 80 + aq[i] * 8) = lo;
        }
        unsigned char* bd = (bbuf ? DSM_BLO(0) : DSM_BHI(0)) + boff;
        *(uint4*)bd        = pb0;
        *(uint4*)(bd + 16) = pb1;
        #pragma unroll
        for (int i = 0; i < 2; i++) {
            int gk = 32 + aq[i] * 4;
            pa[i] = __ldcs((const float4*)(A + (size_t)(row0 + ar[i]) * FIN + gk));
        }
        pb0 = *(const uint4*)(bsrc + (size_t)bn * KPAD + 32 + bhalf * 16);
        pb1 = *(const uint4*)(bsrc + (size_t)bn * KPAD + 32 + bhalf * 16 + 8);
        __syncthreads();

        for (int c = 0; c < KC; c++) {
            int buf = c & 1;
            // ---- store chunk c+1 (in regs) into buf^1 ----
            if (c + 1 < KC) {
                #pragma unroll
                for (int i = 0; i < 2; i++) {
                    uint2 hi, lo; split4(pa[i], hi, lo);
                    *(uint2*)(DSM_AHI(buf ^ 1) + ar[i] * 80 + aq[i] * 8) = hi;
                    *(uint2*)(DSM_ALO(buf ^ 1) + ar[i] * 80 + aq[i] * 8) = lo;
                }
                unsigned char* bd2 = (bbuf ? DSM_BLO(buf ^ 1) : DSM_BHI(buf ^ 1)) + boff;
                *(uint4*)bd2        = pb0;
                *(uint4*)(bd2 + 16) = pb1;
            }
            // ---- prefetch chunk c+2 into regs ----
            if (c + 2 < KC) {
                int k0 = (c + 2) * 32;
                #pragma unroll
                for (int i = 0; i < 2; i++) {
                    int gk = k0 + aq[i] * 4;
                    pa[i] = (gk + 4 <= FIN)
                        ? __ldcs((const float4*)(A + (size_t)(row0 + ar[i]) * FIN + gk))
                        : make_float4(0.f, 0.f, 0.f, 0.f);
                }
                pb0 = *(const uint4*)(bsrc + (size_t)bn * KPAD + k0 + bhalf * 16);
                pb1 = *(const uint4*)(bsrc + (size_t)bn * KPAD + k0 + bhalf * 16 + 8);
            }

            // ---- compute chunk c on buf ----
            const unsigned char* ahi_s = DSM_AHI(buf);
            const unsigned char* alo_s = DSM_ALO(buf);
            const unsigned char* bhi_s = DSM_BHI(buf);
            const unsigned char* blo_s = DSM_BLO(buf);
            #pragma unroll
            for (int ks = 0; ks < 32; ks += 16) {
                int cb = fcb + ks * 2;
                u32 ahi[4], alo[4], bh[4][2], bl[4][2];
                {
                    int r0b = (wm * 16 + fr) * 80 + cb;
                    ahi[0] = *(const u32*)(ahi_s + r0b);
                    ahi[1] = *(const u32*)(ahi_s + r0b + 8 * 80);
                    ahi[2] = *(const u32*)(ahi_s + r0b + 16);
                    ahi[3] = *(const u32*)(ahi_s + r0b + 8 * 80 + 16);
                    alo[0] = *(const u32*)(alo_s + r0b);
                    alo[1] = *(const u32*)(alo_s + r0b + 8 * 80);
                    alo[2] = *(const u32*)(alo_s + r0b + 16);
                    alo[3] = *(const u32*)(alo_s + r0b + 8 * 80 + 16);
                }
                #pragma unroll
                for (int ni = 0; ni < 4; ni++) {
                    int nb = (wn * 32 + ni * 8 + fr) * 80 + cb;
                    bh[ni][0] = *(const u32*)(bhi_s + nb);
                    bh[ni][1] = *(const u32*)(bhi_s + nb + 16);
                    bl[ni][0] = *(const u32*)(blo_s + nb);
                    bl[ni][1] = *(const u32*)(blo_s + nb + 16);
                }
                #pragma unroll
                for (int ni = 0; ni < 4; ni++) {
                    mmabf(d[ni], ahi, bh[ni]);
                    mmabf(d[ni], ahi, bl[ni]);
                    mmabf(d[ni], alo, bh[ni]);
                }
            }
            __syncthreads();
        }

        #pragma unroll
        for (int ni = 0; ni < 4; ni++) {
            int r = row0 + wm * 16 + fr;
            int cc = wn * 32 + ni * 8 + (lane & 3) * 2;
            *(float2*)(C + (size_t)r * FO + cc)       = make_float2(d[ni][0], d[ni][1]);
            *(float2*)(C + (size_t)(r + 8) * FO + cc) = make_float2(d[ni][2], d[ni][3]);
        }
    } else {
        // ------------------- BUILD role -------------------
        int bxx   = bx - 256;
        int which = bxx >> 13;
        int row   = bxx & (NN - 1);
        const float* mat = which ? gnm : adj;
        const float4* rp = (const float4*)(mat + (size_t)row * NN);

        u32 mask = 0u;
        #pragma unroll
        for (int q = 0; q < 8; q++) {
            float4 v = __ldcs(rp + t + 256 * q);
            u32 m4 = (u32)((v.x != 0.f) | ((v.y != 0.f) << 1) |
                           ((v.z != 0.f) << 2) | ((v.w != 0.f) << 3));
            mask |= m4 << (q * 4);
        }
        int c = __popc(mask);

        int lane = t & 31, w = t >> 5;
        int x = c;
        #pragma unroll
        for (int dd = 1; dd < 32; dd <<= 1) {
            int y = __shfl_up_sync(0xffffffffu, x, dd);
            if (lane >= dd) x += y;
        }
        if (lane == 31) wsum[w] = x;
        __syncthreads();
        int base = 0, total = 0;
        #pragma unroll
        for (int i = 0; i < 8; i++) { int s = wsum[i]; base += (i < w) ? s : 0; total += s; }
        int o = base + x - c;

        int* outl = (which ? g_gn_idx : g_adj_idx) + (size_t)row * CAP;
        u32 m = mask;
        int colbase = t * 4;
        while (m) {
            int b = __ffs(m) - 1;
            int col = colbase + ((b >> 2) << 10) + (b & 3);
            if (o < CAP) outl[o] = col;
            o++;
            m &= m - 1;
        }
        if (t == 0) {
            if (which == 0) {
                int tot = total;
                if (tot < CAP) { outl[tot] = row; tot++; }   // self loop
                g_adj_cnt[row] = tot;
                g_dinv[row]    = rsqrtf((float)tot);
            } else {
                g_gn_cnt[row] = total;
            }
        }
    }
}

// ---------------------------------------------------------------------------
// h = Pz @ W2 via bf16-split mma.sync. Tile 64x64, K=64. Smem stride 144B.
// Output stores use __stcs (write-once stream, evict-first).
// ---------------------------------------------------------------------------
__global__ void __launch_bounds__(256) gemm_h_mma(float* __restrict__ outh)
{
    __shared__ __align__(16) unsigned char s_ahi[9216];   // 64 rows x 144B
    __shared__ __align__(16) unsigned char s_alo[9216];
    __shared__ __align__(16) unsigned char s_bhi[9216];
    __shared__ __align__(16) unsigned char s_blo[9216];

    int t = threadIdx.x;
    int wid = t >> 5, lane = t & 31;
    int wm = wid & 1, wn = wid >> 1;        // 2 warps x 32 rows, 4 warps x 16 cols
    int fr = lane >> 2;
    int fcb = (lane & 3) * 4;
    int row0 = blockIdx.x * 64;
    int n0   = blockIdx.y * 64;

    // A: 64 rows x 64 k fp32 -> hi/lo (4 float4/thread)
    #pragma unroll
    for (int i = 0; i < 4; i++) {
        int lin = t + i * 256;
        int r = lin >> 4, q = lin & 15;
        float4 v = *(const float4*)(g_pz + (size_t)(row0 + r) * 64 + q * 4);
        uint2 hi, lo; split4(v, hi, lo);
        *(uint2*)(s_ahi + r * 144 + q * 8) = hi;
        *(uint2*)(s_alo + r * 144 + q * 8) = lo;
    }
    // B: w2t rows [n0, n0+64), 64 k bf16 each (4 uint4/thread across hi/lo)
    #pragma unroll
    for (int i = 0; i < 4; i++) {
        int lin = t + i * 256;
        int buf = lin >> 9, rem = lin & 511;
        int n = rem >> 3, part = rem & 7;
        const __nv_bfloat16* src = buf ? g_w2t_lo : g_w2t_hi;
        uint4 v = *(const uint4*)(src + (size_t)(n0 + n) * 64 + part * 8);
        *(uint4*)((buf ? s_blo : s_bhi) + n * 144 + part * 16) = v;
    }
    __syncthreads();

    float d[2][2][4];
    #pragma unroll
    for (int mi = 0; mi < 2; mi++)
        #pragma unroll
        for (int ni = 0; ni < 2; ni++)
            #pragma unroll
            for (int j = 0; j < 4; j++) d[mi][ni][j] = 0.f;

    #pragma unroll
    for (int ks = 0; ks < 64; ks += 16) {
        int cb = fcb + ks * 2;
        u32 ahi[2][4], alo[2][4], bh[2][2], bl[2][2];
        #pragma unroll
        for (int mi = 0; mi < 2; mi++) {
            int r0b = (wm * 32 + mi * 16 + fr) * 144 + cb;
            ahi[mi][0] = *(const u32*)(s_ahi + r0b);
            ahi[mi][1] = *(const u32*)(s_ahi + r0b + 8 * 144);
            ahi[mi][2] = *(const u32*)(s_ahi + r0b + 16);
            ahi[mi][3] = *(const u32*)(s_ahi + r0b + 8 * 144 + 16);
            alo[mi][0] = *(const u32*)(s_alo + r0b);
            alo[mi][1] = *(const u32*)(s_alo + r0b + 8 * 144);
            alo[mi][2] = *(const u32*)(s_alo + r0b + 16);
            alo[mi][3] = *(const u32*)(s_alo + r0b + 8 * 144 + 16);
        }
        #pragma unroll
        for (int ni = 0; ni < 2; ni++) {
            int nb = (wn * 16 + ni * 8 + fr) * 144 + cb;
            bh[ni][0] = *(const u32*)(s_bhi + nb);
            bh[ni][1] = *(const u32*)(s_bhi + nb + 16);
            bl[ni][0] = *(const u32*)(s_blo + nb);
            bl[ni][1] = *(const u32*)(s_blo + nb + 16);
        }
        #pragma unroll
        for (int mi = 0; mi < 2; mi++)
            #pragma unroll
            for (int ni = 0; ni < 2; ni++) {
                mmabf(d[mi][ni], ahi[mi], bh[ni]);
                mmabf(d[mi][ni], ahi[mi], bl[ni]);
                mmabf(d[mi][ni], alo[mi], bh[ni]);
            }
    }

    #pragma unroll
    for (int mi = 0; mi < 2; mi++)
        #pragma unroll
        for (int ni = 0; ni < 2; ni++) {
            int r = row0 + wm * 32 + mi * 16 + fr;
            int cc = n0 + wn * 16 + ni * 8 + (lane & 3) * 2;
            if (cc < FIN) {
                __stcs((float2*)(outh + (size_t)r * FIN + cc),
                       make_float2(d[mi][ni][0], d[mi][ni][1]));
                __stcs((float2*)(outh + (size_t)(r + 8) * FIN + cc),
                       make_float2(d[mi][ni][2], d[mi][ni][3]));
            }
        }
}

// ---------------------------------------------------------------------------
// z = P@XW1 ; emb = relu(z) ; emb_a = relu(P@XaW1).
// ONE WARP PER ROW, float2 gathers (lane covers cols 2l, 2l+1). No block sync.
// ---------------------------------------------------------------------------
__global__ void __launch_bounds__(128) spmm1_kernel(
    float* __restrict__ out_z, float* __restrict__ out_emb, float* __restrict__ out_emb_a)
{
    int t = threadIdx.x, w = t >> 5, lane = t & 31;
    int row = blockIdx.x * 4 + w;
    __shared__ int   sidx[4][CAP];
    __shared__ float sw[4][CAP];
    const float2* xw1  = (const float2*)g_xw1;
    const float2* xaw1 = (const float2*)g_xaw1;

    int cnt = g_adj_cnt[row];
    for (int k = lane; k < cnt; k += 32) {
        int j = g_adj_idx[row * CAP + k];
        sidx[w][k] = j * 32;            // float2 row base
        sw[w][k]   = g_dinv[j];
    }
    __syncwarp();

    float2 a0 = {0,0}, a1 = {0,0}, a2 = {0,0}, a3 = {0,0};
    float2 b0 = {0,0}, b1 = {0,0}, b2 = {0,0}, b3 = {0,0};
    int k = 0;
    for (; k + 4 <= cnt; k += 4) {
        int j0 = sidx[w][k] + lane,     j1 = sidx[w][k + 1] + lane;
        int j2 = sidx[w][k + 2] + lane, j3 = sidx[w][k + 3] + lane;
        float w0 = sw[w][k], w1 = sw[w][k + 1], w2 = sw[w][k + 2], w3 = sw[w][k + 3];
        float2 v0 = xw1[j0], v1 = xw1[j1], v2 = xw1[j2], v3 = xw1[j3];
        float2 y0 = xaw1[j0], y1 = xaw1[j1], y2 = xaw1[j2], y3 = xaw1[j3];
        a0.x += w0 * v0.x; a0.y += w0 * v0.y;  b0.x += w0 * y0.x; b0.y += w0 * y0.y;
        a1.x += w1 * v1.x; a1.y += w1 * v1.y;  b1.x += w1 * y1.x; b1.y += w1 * y1.y;
        a2.x += w2 * v2.x; a2.y += w2 * v2.y;  b2.x += w2 * y2.x; b2.y += w2 * y2.y;
        a3.x += w3 * v3.x; a3.y += w3 * v3.y;  b3.x += w3 * y3.x; b3.y += w3 * y3.y;
    }
    for (; k < cnt; k++) {
        int j = sidx[w][k] + lane; float ww = sw[w][k];
        float2 v = xw1[j], y = xaw1[j];
        a0.x += ww * v.x; a0.y += ww * v.y;
        b0.x += ww * y.x; b0.y += ww * y.y;
    }
    float di = g_dinv[row];
    float zx = di * ((a0.x + a1.x) + (a2.x + a3.x));
    float zy = di * ((a0.y + a1.y) + (a2.y + a3.y));
    float zax = di * ((b0.x + b1.x) + (b2.x + b3.x));
    float zay = di * ((b0.y + b1.y) + (b2.y + b3.y));
    int o = row * 32 + lane;
    ((float2*)out_z)[o]     = make_float2(zx, zy);
    ((float2*)out_emb)[o]   = make_float2(fmaxf(zx, 0.f), fmaxf(zy, 0.f));
    ((float2*)out_emb_a)[o] = make_float2(fmaxf(zax, 0.f), fmaxf(zay, 0.f));
}

// ---------------------------------------------------------------------------
// Fused: Pz = P@z ; readout ; bilinear discriminator.
// ONE WARP PER ROW, float2 gathers, warp-local shfl reductions. No block sync.
// ---------------------------------------------------------------------------
__global__ void __launch_bounds__(128) spmm2_readout_disc_kernel(
    const float* __restrict__ z, const float* __restrict__ emb,
    const float* __restrict__ emb_a, const float* __restrict__ W,
    const float* __restrict__ bptr,
    float* __restrict__ ret, float* __restrict__ ret_a)
{
    int t = threadIdx.x, w = t >> 5, lane = t & 31;
    int row = blockIdx.x * 4 + w;
    __shared__ int   sidxA[4][CAP];
    __shared__ float swA[4][CAP];
    __shared__ int   sidxG[4][CAP];
    __shared__ float se[4][64], sea[4][64];
    const float2* z2  = (const float2*)z;
    const float2* e2  = (const float2*)emb;
    const float2* ea2 = (const float2*)emb_a;

    int cnt  = g_adj_cnt[row];
    int gcnt = g_gn_cnt[row];
    for (int k = lane; k < cnt; k += 32) {
        int j = g_adj_idx[row * CAP + k];
        sidxA[w][k] = j * 32;
        swA[w][k]   = g_dinv[j];
    }
    for (int k = lane; k < gcnt; k += 32)
        sidxG[w][k] = g_gn_idx[row * CAP + k] * 32;
    {
        float2 ev  = e2[row * 32 + lane];
        float2 eav = ea2[row * 32 + lane];
        se[w][2 * lane] = ev.x;  se[w][2 * lane + 1] = ev.y;
        sea[w][2 * lane] = eav.x; sea[w][2 * lane + 1] = eav.y;
    }
    __syncwarp();

    // --- spmm2: Pz ---
    float2 p0 = {0,0}, p1 = {0,0}, p2 = {0,0}, p3 = {0,0};
    int k = 0;
    for (; k + 4 <= cnt; k += 4) {
        int j0 = sidxA[w][k] + lane,     j1 = sidxA[w][k + 1] + lane;
        int j2 = sidxA[w][k + 2] + lane, j3 = sidxA[w][k + 3] + lane;
        float w0 = swA[w][k], w1 = swA[w][k + 1], w2 = swA[w][k + 2], w3 = swA[w][k + 3];
        float2 v0 = z2[j0], v1 = z2[j1], v2 = z2[j2], v3 = z2[j3];
        p0.x += w0 * v0.x; p0.y += w0 * v0.y;
        p1.x += w1 * v1.x; p1.y += w1 * v1.y;
        p2.x += w2 * v2.x; p2.y += w2 * v2.y;
        p3.x += w3 * v3.x; p3.y += w3 * v3.y;
    }
    for (; k < cnt; k++) {
        int j = sidxA[w][k] + lane; float ww = swA[w][k];
        float2 v = z2[j];
        p0.x += ww * v.x; p0.y += ww * v.y;
    }
    float di = g_dinv[row];
    ((float2*)g_pz)[row * 32 + lane] =
        make_float2(di * ((p0.x + p1.x) + (p2.x + p3.x)),
                    di * ((p0.y + p1.y) + (p2.y + p3.y)));

    // --- readout gathers ---
    float2 s0 = {0,0}, s1 = {0,0}, s2 = {0,0}, s3 = {0,0};
    float2 u0 = {0,0}, u1 = {0,0}, u2 = {0,0}, u3 = {0,0};
    k = 0;
    for (; k + 4 <= gcnt; k += 4) {
        int j0 = sidxG[w][k] + lane,     j1 = sidxG[w][k + 1] + lane;
        int j2 = sidxG[w][k + 2] + lane, j3 = sidxG[w][k + 3] + lane;
        float2 v0 = e2[j0], v1 = e2[j1], v2 = e2[j2], v3 = e2[j3];
        float2 y0 = ea2[j0], y1 = ea2[j1], y2 = ea2[j2], y3 = ea2[j3];
        s0.x += v0.x; s0.y += v0.y;  u0.x += y0.x; u0.y += y0.y;
        s1.x += v1.x; s1.y += v1.y;  u1.x += y1.x; u1.y += y1.y;
        s2.x += v2.x; s2.y += v2.y;  u2.x += y2.x; u2.y += y2.y;
        s3.x += v3.x; s3.y += v3.y;  u3.x += y3.x; u3.y += y3.y;
    }
    for (; k < gcnt; k++) {
        int j = sidxG[w][k] + lane;
        float2 v = e2[j], y = ea2[j];
        s0.x += v.x; s0.y += v.y;  u0.x += y.x; u0.y += y.y;
    }
    float inv = 1.f / (float)gcnt;
    float gvx  = ((s0.x + s1.x) + (s2.x + s3.x)) * inv;
    float gvy  = ((s0.y + s1.y) + (s2.y + s3.y)) * inv;
    float gvax = ((u0.x + u1.x) + (u2.x + u3.x)) * inv;
    float gvay = ((u0.y + u1.y) + (u2.y + u3.y)) * inv;

    // --- norms via warp butterfly ---
    float q1 = gvx * gvx + gvy * gvy;
    float q2 = gvax * gvax + gvay * gvay;
    #pragma unroll
    for (int s = 16; s >= 1; s >>= 1) {
        q1 += __shfl_xor_sync(0xffffffffu, q1, s);
        q2 += __shfl_xor_sync(0xffffffffu, q2, s);
    }
    float in1 = 1.f / fmaxf(sqrtf(q1), 1e-12f);
    float in2 = 1.f / fmaxf(sqrtf(q2), 1e-12f);
    float sgx  = 1.f / (1.f + expf(-gvx  * in1));
    float sgy  = 1.f / (1.f + expf(-gvy  * in1));
    float sgax = 1.f / (1.f + expf(-gvax * in2));
    float sgay = 1.f / (1.f + expf(-gvay * in2));

    // --- discriminator (W via L1/L2-hot LDG, float2) ---
    const float2* W2p = (const float2*)W;
    float vx = 0.f, vy = 0.f, vax = 0.f, vay = 0.f;
    #pragma unroll 8
    for (int dd = 0; dd < 64; dd++) {
        float2 wv = __ldg(W2p + dd * 32 + lane);
        float e = se[w][dd], ea = sea[w][dd];
        vx  += e  * wv.x;  vy  += e  * wv.y;
        vax += ea * wv.x;  vay += ea * wv.y;
    }
    float r0 = vx * sgx + vy * sgy;
    float r1 = vax * sgx + vay * sgy;
    float r2 = vax * sgax + vay * sgay;
    float r3 = vx * sgax + vy * sgay;
    #pragma unroll
    for (int s = 16; s >= 1; s >>= 1) {
        r0 += __shfl_xor_sync(0xffffffffu, r0, s);
        r1 += __shfl_xor_sync(0xffffffffu, r1, s);
        r2 += __shfl_xor_sync(0xffffffffu, r2, s);
        r3 += __shfl_xor_sync(0xffffffffu, r3, s);
    }
    if (lane == 0) {
        float b = bptr[0];
        ret[row * 2 + 0]   = r0 + b;
        ret[row * 2 + 1]   = r1 + b;
        ret_a[row * 2 + 0] = r2 + b;
        ret_a[row * 2 + 1] = r3 + b;
    }
}

// ---------------------------------------------------------------------------
extern "C" void kernel_launch(void* const* d_in, const int* in_sizes, int n_in,
                              void* d_out, int out_size)
{
    const float* feat   = (const float*)d_in[0];
    const float* feat_a = (const float*)d_in[1];
    const float* adj    = (const float*)d_in[2];
    const float* gnm    = (const float*)d_in[3];
    const float* W1     = (const float*)d_in[4];
    const float* W2     = (const float*)d_in[5];
    const float* dW     = (const float*)d_in[6];
    const float* db     = (const float*)d_in[7];
    (void)in_sizes; (void)n_in; (void)out_size;

    float* out       = (float*)d_out;
    float* out_z     = out;                       // [8192,64]
    float* out_h     = out + 524288;              // [8192,3000]
    float* out_ret   = out + 25100288;            // [8192,2]
    float* out_ret_a = out + 25116672;            // [8192,2]
    float* out_emb   = out + 25133056;            // [8192,64]
    float* out_emb_a = out + 25657344;            // [8192,64]

    cudaFuncSetAttribute(fused_build_gemm,
                         cudaFuncAttributeMaxDynamicSharedMemorySize, DSM_BYTES);

    prep_kernel<<<1520, 256>>>(W1, W2);
    fused_build_gemm<<<256 + 2 * NN, 256, DSM_BYTES>>>(feat, feat_a, adj, gnm);
    spmm1_kernel<<<NN / 4, 128>>>(out_z, out_emb, out_emb_a);
    spmm2_readout_disc_kernel<<<NN / 4, 128>>>(out_z, out_emb, out_emb_a, dW, db,
                                               out_ret, out_ret_a);
    gemm_h_mma<<<dim3(128, 47), 256>>>(out_h);
}

// round 15
// speedup vs baseline: 1.0561x; 1.0561x over previous
#include <cuda_runtime.h>
#include <cuda_bf16.h>
#include <math.h>
#include <stdint.h>

#define NN   8192
#define FIN  3000
#define FO   64
#define CAP  192
#define KC   94          // ceil(3000/32) K-chunks for feat GEMM
#define KPAD 3008

typedef unsigned long long u64;
typedef unsigned int       u32;

// ---------------- scratch ----------------
__device__ int   g_adj_idx[NN * CAP];
__device__ int   g_adj_cnt[NN];
__device__ float g_dinv[NN];
__device__ int   g_gn_idx[NN * CAP];
__device__ int   g_gn_cnt[NN];
__device__ float g_xw1[NN * FO];
__device__ float g_xaw1[NN * FO];
__device__ float g_pz[NN * FO];
__device__ __nv_bfloat16 g_w1t_hi[FO * KPAD];   // W1^T  [64][3008]
__device__ __nv_bfloat16 g_w1t_lo[FO * KPAD];
__device__ __nv_bfloat16 g_w2t_hi[3072 * FO];   // W2^T  [3072][64]
__device__ __nv_bfloat16 g_w2t_lo[3072 * FO];

// ---------------- mma.sync (sm_80+ PTX; fragment loads are plain LDS) ------
__device__ __forceinline__ void mmabf(float* d, const u32* a, const u32* b) {
    asm volatile("mma.sync.aligned.m16n8k16.row.col.f32.bf16.bf16.f32 "
                 "{%0,%1,%2,%3},{%4,%5,%6,%7},{%8,%9},{%0,%1,%2,%3};"
                 : "+f"(d[0]), "+f"(d[1]), "+f"(d[2]), "+f"(d[3])
                 : "r"(a[0]), "r"(a[1]), "r"(a[2]), "r"(a[3]), "r"(b[0]), "r"(b[1]));
}

// hi/lo bf16 split of 4 floats, packed as 2x(bf16x2)
__device__ __forceinline__ void split4(float4 v, uint2& hi, uint2& lo) {
    __nv_bfloat16 h0 = __float2bfloat16(v.x), h1 = __float2bfloat16(v.y);
    __nv_bfloat16 h2 = __float2bfloat16(v.z), h3 = __float2bfloat16(v.w);
    __nv_bfloat16 l0 = __float2bfloat16(v.x - __bfloat162float(h0));
    __nv_bfloat16 l1 = __float2bfloat16(v.y - __bfloat162float(h1));
    __nv_bfloat16 l2 = __float2bfloat16(v.z - __bfloat162float(h2));
    __nv_bfloat16 l3 = __float2bfloat16(v.w - __bfloat162float(h3));
    hi.x = ((u32)__bfloat16_as_ushort(h1) << 16) | __bfloat16_as_ushort(h0);
    hi.y = ((u32)__bfloat16_as_ushort(h3) << 16) | __bfloat16_as_ushort(h2);
    lo.x = ((u32)__bfloat16_as_ushort(l1) << 16) | __bfloat16_as_ushort(l0);
    lo.y = ((u32)__bfloat16_as_ushort(l3) << 16) | __bfloat16_as_ushort(l2);
}

// ---------------------------------------------------------------------------
// Prep: W1^T and W2^T as bf16 hi/lo, zero-padded.
// ---------------------------------------------------------------------------
__global__ void prep_kernel(const float* __restrict__ W1, const float* __restrict__ W2)
{
    int bx = blockIdx.x, t = threadIdx.x;
    if (bx < 752) {                 // w1t: 64 x 3008
        int idx = bx * 256 + t;
        int n = idx & 63, k = idx >> 6;
        float x = (k < FIN) ? W1[k * 64 + n] : 0.f;
        __nv_bfloat16 h = __float2bfloat16(x);
        __nv_bfloat16 l = __float2bfloat16(x - __bfloat162float(h));
        g_w1t_hi[n * KPAD + k] = h;
        g_w1t_lo[n * KPAD + k] = l;
    } else {                        // w2t: 3072 x 64
        int idx = (bx - 752) * 256 + t;
        int k = idx & 63, n = idx >> 6;
        float x = (n < FIN) ? W2[k * FIN + n] : 0.f;
        __nv_bfloat16 h = __float2bfloat16(x);
        __nv_bfloat16 l = __float2bfloat16(x - __bfloat162float(h));
        g_w2t_hi[n * 64 + k] = h;
        g_w2t_lo[n * 64 + k] = l;
    }
}

// ---------------------------------------------------------------------------
// Fused: blocks [0,128) = feat@W1 / feat_a@W1 via bf16-split mma.sync;
//        blocks [128, 128+2*NN) = adjacency / graph_neigh ELL builds.
// (ROUND-13 config: 128x64 tiles, 60KB dsm, double-buffered, __ldcs streams.)
// ---------------------------------------------------------------------------
#define DSM_AHI(buf)  (dsm + (buf) * 10240)
#define DSM_ALO(buf)  (dsm + 20480 + (buf) * 10240)
#define DSM_BHI(buf)  (dsm + 40960 + (buf) * 5120)
#define DSM_BLO(buf)  (dsm + 51200 + (buf) * 5120)
#define DSM_BYTES 61440

__global__ void __launch_bounds__(256) fused_build_gemm(
    const float* __restrict__ feat, const float* __restrict__ feat_a,
    const float* __restrict__ adj, const float* __restrict__ gnm)
{
    extern __shared__ __align__(16) unsigned char dsm[];
    __shared__ int wsum[8];

    int t  = threadIdx.x;
    int bx = blockIdx.x;

    if (bx < 128) {
        // ------------------- GEMM role -------------------
        int which = bx >> 6;
        int row0  = (bx & 63) * 128;
        const float* A = which ? feat_a : feat;
        float*       C = which ? g_xaw1 : g_xw1;

        int wid = t >> 5, lane = t & 31;
        int wm = wid & 3, wn = wid >> 2;     // 4 warps x 32 rows, 2 warps x 32 cols
        int fr = lane >> 2;                  // groupID
        int fcb = (lane & 3) * 4;            // k-pair byte offset

        float d[2][4][4];
        #pragma unroll
        for (int mi = 0; mi < 2; mi++)
            #pragma unroll
            for (int ni = 0; ni < 4; ni++)
                #pragma unroll
                for (int j = 0; j < 4; j++) d[mi][ni][j] = 0.f;

        // A-store mapping: 4 float4/thread
        int ar[4], aq[4];
        #pragma unroll
        for (int i = 0; i < 4; i++) { int lin = t + i * 256; ar[i] = lin >> 3; aq[i] = lin & 7; }
        // B: 2 threads/row, each moves 2 uint4 (32 B) -> full 64-B row covered
        int bi = t & 127, bn = bi >> 1, bhalf = bi & 1, bbuf = t >> 7;
        const __nv_bfloat16* bsrc = bbuf ? g_w1t_lo : g_w1t_hi;
        int boff = bn * 80 + bhalf * 32;

        float4 pa[4]; uint4 pb0, pb1;
        // ---- prologue: chunk 0 -> buf0; prefetch chunk 1 into regs ----
        #pragma unroll
        for (int i = 0; i < 4; i++)
            pa[i] = __ldcs((const float4*)(A + (size_t)(row0 + ar[i]) * FIN + aq[i] * 4));
        pb0 = *(const uint4*)(bsrc + (size_t)bn * KPAD + bhalf * 16);
        pb1 = *(const uint4*)(bsrc + (size_t)bn * KPAD + bhalf * 16 + 8);
        #pragma unroll
        for (int i = 0; i < 4; i++) {
            uint2 hi, lo; split4(pa[i], hi, lo);
            *(uint2*)(DSM_AHI(0) + ar[i] * 80 + aq[i] * 8) = hi;
            *(uint2*)(DSM_ALO(0) + ar[i] * 80 + aq[i] * 8) = lo;
        }
        unsigned char* bd = (bbuf ? DSM_BLO(0) : DSM_BHI(0)) + boff;
        *(uint4*)bd        = pb0;
        *(uint4*)(bd + 16) = pb1;
        #pragma unroll
        for (int i = 0; i < 4; i++) {
            int gk = 32 + aq[i] * 4;
            pa[i] = __ldcs((const float4*)(A + (size_t)(row0 + ar[i]) * FIN + gk));
        }
        pb0 = *(const uint4*)(bsrc + (size_t)bn * KPAD + 32 + bhalf * 16);
        pb1 = *(const uint4*)(bsrc + (size_t)bn * KPAD + 32 + bhalf * 16 + 8);
        __syncthreads();

        for (int c = 0; c < KC; c++) {
            int buf = c & 1;
            // ---- store chunk c+1 (in regs) into buf^1 ----
            if (c + 1 < KC) {
                #pragma unroll
                for (int i = 0; i < 4; i++) {
                    uint2 hi, lo; split4(pa[i], hi, lo);
                    *(uint2*)(DSM_AHI(buf ^ 1) + ar[i] * 80 + aq[i] * 8) = hi;
                    *(uint2*)(DSM_ALO(buf ^ 1) + ar[i] * 80 + aq[i] * 8) = lo;
                }
                unsigned char* bd2 = (bbuf ? DSM_BLO(buf ^ 1) : DSM_BHI(buf ^ 1)) + boff;
                *(uint4*)bd2        = pb0;
                *(uint4*)(bd2 + 16) = pb1;
            }
            // ---- prefetch chunk c+2 into regs ----
            if (c + 2 < KC) {
                int k0 = (c + 2) * 32;
                #pragma unroll
                for (int i = 0; i < 4; i++) {
                    int gk = k0 + aq[i] * 4;
                    pa[i] = (gk + 4 <= FIN)
                        ? __ldcs((const float4*)(A + (size_t)(row0 + ar[i]) * FIN + gk))
                        : make_float4(0.f, 0.f, 0.f, 0.f);
                }
                pb0 = *(const uint4*)(bsrc + (size_t)bn * KPAD + k0 + bhalf * 16);
                pb1 = *(const uint4*)(bsrc + (size_t)bn * KPAD + k0 + bhalf * 16 + 8);
            }

            // ---- compute chunk c on buf ----
            const unsigned char* ahi_s = DSM_AHI(buf);
            const unsigned char* alo_s = DSM_ALO(buf);
            const unsigned char* bhi_s = DSM_BHI(buf);
            const unsigned char* blo_s = DSM_BLO(buf);
            #pragma unroll
            for (int ks = 0; ks < 32; ks += 16) {
                int cb = fcb + ks * 2;
                u32 ahi[2][4], alo[2][4], bh[4][2], bl[4][2];
                #pragma unroll
                for (int mi = 0; mi < 2; mi++) {
                    int r0b = (wm * 32 + mi * 16 + fr) * 80 + cb;
                    ahi[mi][0] = *(const u32*)(ahi_s + r0b);
                    ahi[mi][1] = *(const u32*)(ahi_s + r0b + 8 * 80);
                    ahi[mi][2] = *(const u32*)(ahi_s + r0b + 16);
                    ahi[mi][3] = *(const u32*)(ahi_s + r0b + 8 * 80 + 16);
                    alo[mi][0] = *(const u32*)(alo_s + r0b);
                    alo[mi][1] = *(const u32*)(alo_s + r0b + 8 * 80);
                    alo[mi][2] = *(const u32*)(alo_s + r0b + 16);
                    alo[mi][3] = *(const u32*)(alo_s + r0b + 8 * 80 + 16);
                }
                #pragma unroll
                for (int ni = 0; ni < 4; ni++) {
                    int nb = (wn * 32 + ni * 8 + fr) * 80 + cb;
                    bh[ni][0] = *(const u32*)(bhi_s + nb);
                    bh[ni][1] = *(const u32*)(bhi_s + nb + 16);
                    bl[ni][0] = *(const u32*)(blo_s + nb);
                    bl[ni][1] = *(const u32*)(blo_s + nb + 16);
                }
                #pragma unroll
                for (int mi = 0; mi < 2; mi++)
                    #pragma unroll
                    for (int ni = 0; ni < 4; ni++) {
                        mmabf(d[mi][ni], ahi[mi], bh[ni]);
                        mmabf(d[mi][ni], ahi[mi], bl[ni]);
                        mmabf(d[mi][ni], alo[mi], bh[ni]);
                    }
            }
            __syncthreads();
        }

        #pragma unroll
        for (int mi = 0; mi < 2; mi++)
            #pragma unroll
            for (int ni = 0; ni < 4; ni++) {
                int r = row0 + wm * 32 + mi * 16 + fr;
                int cc = wn * 32 + ni * 8 + (lane & 3) * 2;
                *(float2*)(C + (size_t)r * FO + cc)       = make_float2(d[mi][ni][0], d[mi][ni][1]);
                *(float2*)(C + (size_t)(r + 8) * FO + cc) = make_float2(d[mi][ni][2], d[mi][ni][3]);
            }
    } else {
        // ------------------- BUILD role -------------------
        int bxx   = bx - 128;
        int which = bxx >> 13;
        int row   = bxx & (NN - 1);
        const float* mat = which ? gnm : adj;
        const float4* rp = (const float4*)(mat + (size_t)row * NN);

        u32 mask = 0u;
        #pragma unroll
        for (int q = 0; q < 8; q++) {
            float4 v = __ldcs(rp + t + 256 * q);
            u32 m4 = (u32)((v.x != 0.f) | ((v.y != 0.f) << 1) |
                           ((v.z != 0.f) << 2) | ((v.w != 0.f) << 3));
            mask |= m4 << (q * 4);
        }
        int c = __popc(mask);

        int lane = t & 31, w = t >> 5;
        int x = c;
        #pragma unroll
        for (int dd = 1; dd < 32; dd <<= 1) {
            int y = __shfl_up_sync(0xffffffffu, x, dd);
            if (lane >= dd) x += y;
        }
        if (lane == 31) wsum[w] = x;
        __syncthreads();
        int base = 0, total = 0;
        #pragma unroll
        for (int i = 0; i < 8; i++) { int s = wsum[i]; base += (i < w) ? s : 0; total += s; }
        int o = base + x - c;

        int* outl = (which ? g_gn_idx : g_adj_idx) + (size_t)row * CAP;
        u32 m = mask;
        int colbase = t * 4;
        while (m) {
            int b = __ffs(m) - 1;
            int col = colbase + ((b >> 2) << 10) + (b & 3);
            if (o < CAP) outl[o] = col;
            o++;
            m &= m - 1;
        }
        if (t == 0) {
            if (which == 0) {
                int tot = total;
                if (tot < CAP) { outl[tot] = row; tot++; }   // self loop
                g_adj_cnt[row] = tot;
                g_dinv[row]    = rsqrtf((float)tot);
            } else {
                g_gn_cnt[row] = total;
            }
        }
    }
}

// ---------------------------------------------------------------------------
// h = Pz @ W2 via bf16-split mma.sync. NEW: 128x64 tile (grid 64x47),
// dynamic smem 55KB; B-tile L2 re-reads halved; warp layout = proven 2x4.
// ---------------------------------------------------------------------------
#define HSM_AHI  (hsm)                     // 128 rows x 144B
#define HSM_ALO  (hsm + 18432)
#define HSM_BHI  (hsm + 36864)             // 64 rows x 144B
#define HSM_BLO  (hsm + 46080)
#define HSM_BYTES 55296

__global__ void __launch_bounds__(256) gemm_h_mma(float* __restrict__ outh)
{
    extern __shared__ __align__(16) unsigned char hsm[];

    int t = threadIdx.x;
    int wid = t >> 5, lane = t & 31;
    int wm = wid & 3, wn = wid >> 2;        // 4 warps x 32 rows, 2 warps x 32 cols
    int fr = lane >> 2;
    int fcb = (lane & 3) * 4;
    int row0 = blockIdx.x * 128;
    int n0   = blockIdx.y * 64;

    // A: 128 rows x 64 k fp32 -> hi/lo (8 float4/thread)
    #pragma unroll
    for (int i = 0; i < 8; i++) {
        int lin = t + i * 256;
        int r = lin >> 4, q = lin & 15;
        float4 v = *(const float4*)(g_pz + (size_t)(row0 + r) * 64 + q * 4);
        uint2 hi, lo; split4(v, hi, lo);
        *(uint2*)(HSM_AHI + r * 144 + q * 8) = hi;
        *(uint2*)(HSM_ALO + r * 144 + q * 8) = lo;
    }
    // B: w2t rows [n0, n0+64), 64 k bf16 each (4 uint4/thread across hi/lo)
    #pragma unroll
    for (int i = 0; i < 4; i++) {
        int lin = t + i * 256;
        int buf = lin >> 9, rem = lin & 511;
        int n = rem >> 3, part = rem & 7;
        const __nv_bfloat16* src = buf ? g_w2t_lo : g_w2t_hi;
        uint4 v = *(const uint4*)(src + (size_t)(n0 + n) * 64 + part * 8);
        *(uint4*)((buf ? HSM_BLO : HSM_BHI) + n * 144 + part * 16) = v;
    }
    __syncthreads();

    float d[2][4][4];
    #pragma unroll
    for (int mi = 0; mi < 2; mi++)
        #pragma unroll
        for (int ni = 0; ni < 4; ni++)
            #pragma unroll
            for (int j = 0; j < 4; j++) d[mi][ni][j] = 0.f;

    #pragma unroll
    for (int ks = 0; ks < 64; ks += 16) {
        int cb = fcb + ks * 2;
        u32 ahi[2][4], alo[2][4], bh[4][2], bl[4][2];
        #pragma unroll
        for (int mi = 0; mi < 2; mi++) {
            int r0b = (wm * 32 + mi * 16 + fr) * 144 + cb;
            ahi[mi][0] = *(const u32*)(HSM_AHI + r0b);
            ahi[mi][1] = *(const u32*)(HSM_AHI + r0b + 8 * 144);
            ahi[mi][2] = *(const u32*)(HSM_AHI + r0b + 16);
            ahi[mi][3] = *(const u32*)(HSM_AHI + r0b + 8 * 144 + 16);
            alo[mi][0] = *(const u32*)(HSM_ALO + r0b);
            alo[mi][1] = *(const u32*)(HSM_ALO + r0b + 8 * 144);
            alo[mi][2] = *(const u32*)(HSM_ALO + r0b + 16);
            alo[mi][3] = *(const u32*)(HSM_ALO + r0b + 8 * 144 + 16);
        }
        #pragma unroll
        for (int ni = 0; ni < 4; ni++) {
            int nb = (wn * 32 + ni * 8 + fr) * 144 + cb;
            bh[ni][0] = *(const u32*)(HSM_BHI + nb);
            bh[ni][1] = *(const u32*)(HSM_BHI + nb + 16);
            bl[ni][0] = *(const u32*)(HSM_BLO + nb);
            bl[ni][1] = *(const u32*)(HSM_BLO + nb + 16);
        }
        #pragma unroll
        for (int mi = 0; mi < 2; mi++)
            #pragma unroll
            for (int ni = 0; ni < 4; ni++) {
                mmabf(d[mi][ni], ahi[mi], bh[ni]);
                mmabf(d[mi][ni], ahi[mi], bl[ni]);
                mmabf(d[mi][ni], alo[mi], bh[ni]);
            }
    }

    #pragma unroll
    for (int mi = 0; mi < 2; mi++)
        #pragma unroll
        for (int ni = 0; ni < 4; ni++) {
            int r = row0 + wm * 32 + mi * 16 + fr;
            int cc = n0 + wn * 32 + ni * 8 + (lane & 3) * 2;
            if (cc < FIN) {
                __stcs((float2*)(outh + (size_t)r * FIN + cc),
                       make_float2(d[mi][ni][0], d[mi][ni][1]));
                __stcs((float2*)(outh + (size_t)(r + 8) * FIN + cc),
                       make_float2(d[mi][ni][2], d[mi][ni][3]));
            }
        }
}

// ---------------------------------------------------------------------------
// z = P@XW1 ; emb = relu(z) ; emb_a = relu(P@XaW1).
// ONE WARP PER ROW, float2 gathers. No block sync.
// ---------------------------------------------------------------------------
__global__ void __launch_bounds__(128) spmm1_kernel(
    float* __restrict__ out_z, float* __restrict__ out_emb, float* __restrict__ out_emb_a)
{
    int t = threadIdx.x, w = t >> 5, lane = t & 31;
    int row = blockIdx.x * 4 + w;
    __shared__ int   sidx[4][CAP];
    __shared__ float sw[4][CAP];
    const float2* xw1  = (const float2*)g_xw1;
    const float2* xaw1 = (const float2*)g_xaw1;

    int cnt = g_adj_cnt[row];
    for (int k = lane; k < cnt; k += 32) {
        int j = g_adj_idx[row * CAP + k];
        sidx[w][k] = j * 32;            // float2 row base
        sw[w][k]   = g_dinv[j];
    }
    __syncwarp();

    float2 a0 = {0,0}, a1 = {0,0}, a2 = {0,0}, a3 = {0,0};
    float2 b0 = {0,0}, b1 = {0,0}, b2 = {0,0}, b3 = {0,0};
    int k = 0;
    for (; k + 4 <= cnt; k += 4) {
        int j0 = sidx[w][k] + lane,     j1 = sidx[w][k + 1] + lane;
        int j2 = sidx[w][k + 2] + lane, j3 = sidx[w][k + 3] + lane;
        float w0 = sw[w][k], w1 = sw[w][k + 1], w2 = sw[w][k + 2], w3 = sw[w][k + 3];
        float2 v0 = xw1[j0], v1 = xw1[j1], v2 = xw1[j2], v3 = xw1[j3];
        float2 y0 = xaw1[j0], y1 = xaw1[j1], y2 = xaw1[j2], y3 = xaw1[j3];
        a0.x += w0 * v0.x; a0.y += w0 * v0.y;  b0.x += w0 * y0.x; b0.y += w0 * y0.y;
        a1.x += w1 * v1.x; a1.y += w1 * v1.y;  b1.x += w1 * y1.x; b1.y += w1 * y1.y;
        a2.x += w2 * v2.x; a2.y += w2 * v2.y;  b2.x += w2 * y2.x; b2.y += w2 * y2.y;
        a3.x += w3 * v3.x; a3.y += w3 * v3.y;  b3.x += w3 * y3.x; b3.y += w3 * y3.y;
    }
    for (; k < cnt; k++) {
        int j = sidx[w][k] + lane; float ww = sw[w][k];
        float2 v = xw1[j], y = xaw1[j];
        a0.x += ww * v.x; a0.y += ww * v.y;
        b0.x += ww * y.x; b0.y += ww * y.y;
    }
    float di = g_dinv[row];
    float zx = di * ((a0.x + a1.x) + (a2.x + a3.x));
    float zy = di * ((a0.y + a1.y) + (a2.y + a3.y));
    float zax = di * ((b0.x + b1.x) + (b2.x + b3.x));
    float zay = di * ((b0.y + b1.y) + (b2.y + b3.y));
    int o = row * 32 + lane;
    ((float2*)out_z)[o]     = make_float2(zx, zy);
    ((float2*)out_emb)[o]   = make_float2(fmaxf(zx, 0.f), fmaxf(zy, 0.f));
    ((float2*)out_emb_a)[o] = make_float2(fmaxf(zax, 0.f), fmaxf(zay, 0.f));
}

// ---------------------------------------------------------------------------
// Fused: Pz = P@z ; readout ; bilinear discriminator.
// ONE WARP PER ROW, float2 gathers, warp-local shfl reductions. No block sync.
// ---------------------------------------------------------------------------
__global__ void __launch_bounds__(128) spmm2_readout_disc_kernel(
    const float* __restrict__ z, const float* __restrict__ emb,
    const float* __restrict__ emb_a, const float* __restrict__ W,
    const float* __restrict__ bptr,
    float* __restrict__ ret, float* __restrict__ ret_a)
{
    int t = threadIdx.x, w = t >> 5, lane = t & 31;
    int row = blockIdx.x * 4 + w;
    __shared__ int   sidxA[4][CAP];
    __shared__ float swA[4][CAP];
    __shared__ int   sidxG[4][CAP];
    __shared__ float se[4][64], sea[4][64];
    const float2* z2  = (const float2*)z;
    const float2* e2  = (const float2*)emb;
    const float2* ea2 = (const float2*)emb_a;

    int cnt  = g_adj_cnt[row];
    int gcnt = g_gn_cnt[row];
    for (int k = lane; k < cnt; k += 32) {
        int j = g_adj_idx[row * CAP + k];
        sidxA[w][k] = j * 32;
        swA[w][k]   = g_dinv[j];
    }
    for (int k = lane; k < gcnt; k += 32)
        sidxG[w][k] = g_gn_idx[row * CAP + k] * 32;
    {
        float2 ev  = e2[row * 32 + lane];
        float2 eav = ea2[row * 32 + lane];
        se[w][2 * lane] = ev.x;  se[w][2 * lane + 1] = ev.y;
        sea[w][2 * lane] = eav.x; sea[w][2 * lane + 1] = eav.y;
    }
    __syncwarp();

    // --- spmm2: Pz ---
    float2 p0 = {0,0}, p1 = {0,0}, p2 = {0,0}, p3 = {0,0};
    int k = 0;
    for (; k + 4 <= cnt; k += 4) {
        int j0 = sidxA[w][k] + lane,     j1 = sidxA[w][k + 1] + lane;
        int j2 = sidxA[w][k + 2] + lane, j3 = sidxA[w][k + 3] + lane;
        float w0 = swA[w][k], w1 = swA[w][k + 1], w2 = swA[w][k + 2], w3 = swA[w][k + 3];
        float2 v0 = z2[j0], v1 = z2[j1], v2 = z2[j2], v3 = z2[j3];
        p0.x += w0 * v0.x; p0.y += w0 * v0.y;
        p1.x += w1 * v1.x; p1.y += w1 * v1.y;
        p2.x += w2 * v2.x; p2.y += w2 * v2.y;
        p3.x += w3 * v3.x; p3.y += w3 * v3.y;
    }
    for (; k < cnt; k++) {
        int j = sidxA[w][k] + lane; float ww = swA[w][k];
        float2 v = z2[j];
        p0.x += ww * v.x; p0.y += ww * v.y;
    }
    float di = g_dinv[row];
    ((float2*)g_pz)[row * 32 + lane] =
        make_float2(di * ((p0.x + p1.x) + (p2.x + p3.x)),
                    di * ((p0.y + p1.y) + (p2.y + p3.y)));

    // --- readout gathers ---
    float2 s0 = {0,0}, s1 = {0,0}, s2 = {0,0}, s3 = {0,0};
    float2 u0 = {0,0}, u1 = {0,0}, u2 = {0,0}, u3 = {0,0};
    k = 0;
    for (; k + 4 <= gcnt; k += 4) {
        int j0 = sidxG[w][k] + lane,     j1 = sidxG[w][k + 1] + lane;
        int j2 = sidxG[w][k + 2] + lane, j3 = sidxG[w][k + 3] + lane;
        float2 v0 = e2[j0], v1 = e2[j1], v2 = e2[j2], v3 = e2[j3];
        float2 y0 = ea2[j0], y1 = ea2[j1], y2 = ea2[j2], y3 = ea2[j3];
        s0.x += v0.x; s0.y += v0.y;  u0.x += y0.x; u0.y += y0.y;
        s1.x += v1.x; s1.y += v1.y;  u1.x += y1.x; u1.y += y1.y;
        s2.x += v2.x; s2.y += v2.y;  u2.x += y2.x; u2.y += y2.y;
        s3.x += v3.x; s3.y += v3.y;  u3.x += y3.x; u3.y += y3.y;
    }
    for (; k < gcnt; k++) {
        int j = sidxG[w][k] + lane;
        float2 v = e2[j], y = ea2[j];
        s0.x += v.x; s0.y += v.y;  u0.x += y.x; u0.y += y.y;
    }
    float inv = 1.f / (float)gcnt;
    float gvx  = ((s0.x + s1.x) + (s2.x + s3.x)) * inv;
    float gvy  = ((s0.y + s1.y) + (s2.y + s3.y)) * inv;
    float gvax = ((u0.x + u1.x) + (u2.x + u3.x)) * inv;
    float gvay = ((u0.y + u1.y) + (u2.y + u3.y)) * inv;

    // --- norms via warp butterfly ---
    float q1 = gvx * gvx + gvy * gvy;
    float q2 = gvax * gvax + gvay * gvay;
    #pragma unroll
    for (int s = 16; s >= 1; s >>= 1) {
        q1 += __shfl_xor_sync(0xffffffffu, q1, s);
        q2 += __shfl_xor_sync(0xffffffffu, q2, s);
    }
    float in1 = 1.f / fmaxf(sqrtf(q1), 1e-12f);
    float in2 = 1.f / fmaxf(sqrtf(q2), 1e-12f);
    float sgx  = 1.f / (1.f + expf(-gvx  * in1));
    float sgy  = 1.f / (1.f + expf(-gvy  * in1));
    float sgax = 1.f / (1.f + expf(-gvax * in2));
    float sgay = 1.f / (1.f + expf(-gvay * in2));

    // --- discriminator (W via L1/L2-hot LDG, float2) ---
    const float2* W2p = (const float2*)W;
    float vx = 0.f, vy = 0.f, vax = 0.f, vay = 0.f;
    #pragma unroll 8
    for (int dd = 0; dd < 64; dd++) {
        float2 wv = __ldg(W2p + dd * 32 + lane);
        float e = se[w][dd], ea = sea[w][dd];
        vx  += e  * wv.x;  vy  += e  * wv.y;
        vax += ea * wv.x;  vay += ea * wv.y;
    }
    float r0 = vx * sgx + vy * sgy;
    float r1 = vax * sgx + vay * sgy;
    float r2 = vax * sgax + vay * sgay;
    float r3 = vx * sgax + vy * sgay;
    #pragma unroll
    for (int s = 16; s >= 1; s >>= 1) {
        r0 += __shfl_xor_sync(0xffffffffu, r0, s);
        r1 += __shfl_xor_sync(0xffffffffu, r1, s);
        r2 += __shfl_xor_sync(0xffffffffu, r2, s);
        r3 += __shfl_xor_sync(0xffffffffu, r3, s);
    }
    if (lane == 0) {
        float b = bptr[0];
        ret[row * 2 + 0]   = r0 + b;
        ret[row * 2 + 1]   = r1 + b;
        ret_a[row * 2 + 0] = r2 + b;
        ret_a[row * 2 + 1] = r3 + b;
    }
}

// ---------------------------------------------------------------------------
extern "C" void kernel_launch(void* const* d_in, const int* in_sizes, int n_in,
                              void* d_out, int out_size)
{
    const float* feat   = (const float*)d_in[0];
    const float* feat_a = (const float*)d_in[1];
    const float* adj    = (const float*)d_in[2];
    const float* gnm    = (const float*)d_in[3];
    const float* W1     = (const float*)d_in[4];
    const float* W2     = (const float*)d_in[5];
    const float* dW     = (const float*)d_in[6];
    const float* db     = (const float*)d_in[7];
    (void)in_sizes; (void)n_in; (void)out_size;

    float* out       = (float*)d_out;
    float* out_z     = out;                       // [8192,64]
    float* out_h     = out + 524288;              // [8192,3000]
    float* out_ret   = out + 25100288;            // [8192,2]
    float* out_ret_a = out + 25116672;            // [8192,2]
    float* out_emb   = out + 25133056;            // [8192,64]
    float* out_emb_a = out + 25657344;            // [8192,64]

    cudaFuncSetAttribute(fused_build_gemm,
                         cudaFuncAttributeMaxDynamicSharedMemorySize, DSM_BYTES);
    cudaFuncSetAttribute(gemm_h_mma,
                         cudaFuncAttributeMaxDynamicSharedMemorySize, HSM_BYTES);

    prep_kernel<<<1520, 256>>>(W1, W2);
    fused_build_gemm<<<128 + 2 * NN, 256, DSM_BYTES>>>(feat, feat_a, adj, gnm);
    spmm1_kernel<<<NN / 4, 128>>>(out_z, out_emb, out_emb_a);
    spmm2_readout_disc_kernel<<<NN / 4, 128>>>(out_z, out_emb, out_emb_a, dW, db,
                                               out_ret, out_ret_a);
    gemm_h_mma<<<dim3(64, 47), 256, HSM_BYTES>>>(out_h);
}